// round 15
// baseline (speedup 1.0000x reference)
#include <cuda_runtime.h>
#include <cuda_bf16.h>
#include <math.h>
#include <stdint.h>

#define Bc 2
#define Sc 2048
#define Dc 1024
#define Hc 16
#define DPc 64

static const size_t SZ_QKV  = (size_t)Bc * Sc * Dc;        // 4194304
static const size_t SZ_ATTN = (size_t)Bc * Hc * Sc * Sc;   // 134217728
#define MD  ((size_t)4194304)
#define DD  ((size_t)1048576)

__device__ __nv_bfloat16 g_iah[3 * MD], g_ial[3 * MD];
__device__ __nv_bfloat16 g_wh[4 * DD],  g_wl[4 * DD];
__device__ __nv_bfloat16 g_qh[MD], g_ql[MD];
__device__ __nv_bfloat16 g_kh[MD], g_kl[MD];
__device__ __nv_bfloat16 g_vh[MD], g_vl[MD];
__device__ __nv_bfloat16 g_ch2[MD], g_cl2[MD];

// ---------------------------------------------------------------------------
__device__ __forceinline__ uint32_t smem_u32(const void* p) {
    uint32_t a;
    asm("{ .reg .u64 t; cvta.to.shared.u64 t, %1; cvt.u32.u64 %0, t; }"
        : "=r"(a) : "l"(p));
    return a;
}
__device__ __forceinline__ void mma16816(float* d, const uint32_t* a, const uint32_t* b) {
    asm volatile(
        "mma.sync.aligned.m16n8k16.row.col.f32.bf16.bf16.f32 "
        "{%0,%1,%2,%3}, {%4,%5,%6,%7}, {%8,%9}, {%0,%1,%2,%3};"
        : "+f"(d[0]), "+f"(d[1]), "+f"(d[2]), "+f"(d[3])
        : "r"(a[0]), "r"(a[1]), "r"(a[2]), "r"(a[3]), "r"(b[0]), "r"(b[1]));
}
__device__ __forceinline__ void ldsm4(uint32_t* r, uint32_t addr) {
    asm volatile("ldmatrix.sync.aligned.m8n8.x4.shared.b16 {%0,%1,%2,%3}, [%4];"
                 : "=r"(r[0]), "=r"(r[1]), "=r"(r[2]), "=r"(r[3]) : "r"(addr));
}
__device__ __forceinline__ void ldsm4t(uint32_t* r, uint32_t addr) {
    asm volatile("ldmatrix.sync.aligned.m8n8.x4.trans.shared.b16 {%0,%1,%2,%3}, [%4];"
                 : "=r"(r[0]), "=r"(r[1]), "=r"(r[2]), "=r"(r[3]) : "r"(addr));
}
__device__ __forceinline__ float fexp2(float x) {
    float r;
    asm("ex2.approx.f32 %0, %1;" : "=f"(r) : "f"(x));
    return r;
}
__device__ __forceinline__ uint32_t pack_hi(float x, float y) {
    __nv_bfloat162 h = __float22bfloat162_rn(make_float2(x, y));
    return *(uint32_t*)&h;
}
__device__ __forceinline__ uint32_t pack_lo(float x, float y) {
    __nv_bfloat16 hx = __float2bfloat16(x), hy = __float2bfloat16(y);
    __nv_bfloat162 l = __float22bfloat162_rn(
        make_float2(x - __bfloat162float(hx), y - __bfloat162float(hy)));
    return *(uint32_t*)&l;
}
__device__ __forceinline__ void cpa16(uint32_t s, const void* g) {
    asm volatile("cp.async.cg.shared.global [%0], [%1], 16;" :: "r"(s), "l"(g));
}
#define CP_COMMIT()  asm volatile("cp.async.commit_group;" ::: "memory")
#define CP_WAITG(n)  asm volatile("cp.async.wait_group %0;" :: "n"(n) : "memory")

// ---------------------------------------------------------------------------
// converts
// ---------------------------------------------------------------------------
struct ConvJob { const float* src; __nv_bfloat16 *h, *l; int n4; };
struct ConvBatch { ConvJob j[7]; };

__global__ __launch_bounds__(256, 4)
void convert_all(ConvBatch cb)
{
    ConvJob jb = cb.j[blockIdx.z];
    int i = blockIdx.x * 256 + threadIdx.x;
    if (i >= jb.n4) return;
    float4 v = ((const float4*)jb.src)[i];
    uint2 H, L;
    H.x = pack_hi(v.x, v.y); H.y = pack_hi(v.z, v.w);
    L.x = pack_lo(v.x, v.y); L.y = pack_lo(v.z, v.w);
    ((uint2*)jb.h)[i] = H;
    ((uint2*)jb.l)[i] = L;
}

// ---------------------------------------------------------------------------
// GEMM v2.1 (unchanged from R14)
// ---------------------------------------------------------------------------
#define G2ROWB 144
#define G2PLANE (128 * G2ROWB)
#define G2STAGE (4 * G2PLANE)
#define G2SM   (3 * G2STAGE)

struct GemmJob {
    const __nv_bfloat16 *Ah, *Al, *Bh, *Bl;
    const float* bias;
    float* C;
    __nv_bfloat16 *Ch, *Cl;
};
struct GemmBatch { GemmJob j[3]; };

__global__ __launch_bounds__(512, 1)
void gemm_bf16(GemmBatch gb, int M, int N, int K)
{
    extern __shared__ __align__(128) char sm[];
    const uint32_t smb = smem_u32(sm);
    const GemmJob jb = gb.j[blockIdx.z];
    const int tid = threadIdx.x;
    const int wid = tid >> 5, lane = tid & 31;
    const int m0 = blockIdx.y * 128, n0 = blockIdx.x * 128;
    const int warp_m = (wid & 3) * 32;
    const int warp_n = (wid >> 2) * 32;
    const int nch = K / 64;

    const __nv_bfloat16* bases[4] = { jb.Ah, jb.Al, jb.Bh, jb.Bl };

    auto issue = [&](int ch) {
        const uint32_t sb = smb + (uint32_t)((ch % 3) * G2STAGE);
        const size_t gk = (size_t)ch * 64;
#pragma unroll
        for (int p = 0; p < 4; p++) {
            const int rbase = (p < 2) ? m0 : n0;
#pragma unroll
            for (int e = 0; e < 2; e++) {
                int idx = tid + e * 512;
                int r = idx >> 3, c = idx & 7;
                cpa16(sb + (uint32_t)(p * G2PLANE + r * G2ROWB + c * 16),
                      bases[p] + (size_t)(rbase + r) * K + gk + c * 8);
            }
        }
    };

    float acc[2][4][4];
#pragma unroll
    for (int i = 0; i < 2; i++)
#pragma unroll
        for (int j = 0; j < 4; j++)
#pragma unroll
            for (int c = 0; c < 4; c++) acc[i][j][c] = 0.0f;

    issue(0); CP_COMMIT();
    issue(1); CP_COMMIT();

    const int arow = lane & 15;
    const int acol = (lane >> 4) * 8;
    const int bg = lane >> 3, bw = lane & 7;

    for (int ch = 0; ch < nch; ch++) {
        CP_WAITG(1);
        __syncthreads();
        if (ch + 2 < nch) issue(ch + 2);
        CP_COMMIT();

        const uint32_t sb = smb + (uint32_t)((ch % 3) * G2STAGE);
#pragma unroll
        for (int ks = 0; ks < 4; ks++) {
            const int k16 = ks * 16;
            uint32_t ah[2][4], al[2][4];
#pragma unroll
            for (int mt = 0; mt < 2; mt++) {
                uint32_t off = (uint32_t)((warp_m + mt * 16 + arow) * G2ROWB
                                          + (k16 + acol) * 2);
                ldsm4(ah[mt], sb + 0 * G2PLANE + off);
                ldsm4(al[mt], sb + 1 * G2PLANE + off);
            }
            uint32_t bh[4][2], bl[4][2];
#pragma unroll
            for (int nb = 0; nb < 2; nb++) {
                uint32_t off = (uint32_t)((warp_n + nb * 16 + (bg & 1) * 8 + bw) * G2ROWB
                                          + (k16 + (bg >> 1) * 8) * 2);
                uint32_t t[4];
                ldsm4(t, sb + 2 * G2PLANE + off);
                bh[nb * 2 + 0][0] = t[0]; bh[nb * 2 + 0][1] = t[2];
                bh[nb * 2 + 1][0] = t[1]; bh[nb * 2 + 1][1] = t[3];
                ldsm4(t, sb + 3 * G2PLANE + off);
                bl[nb * 2 + 0][0] = t[0]; bl[nb * 2 + 0][1] = t[2];
                bl[nb * 2 + 1][0] = t[1]; bl[nb * 2 + 1][1] = t[3];
            }
#pragma unroll
            for (int mt = 0; mt < 2; mt++)
#pragma unroll
                for (int nt = 0; nt < 4; nt++) {
                    mma16816(acc[mt][nt], ah[mt], bh[nt]);
                    mma16816(acc[mt][nt], ah[mt], bl[nt]);
                    mma16816(acc[mt][nt], al[mt], bh[nt]);
                }
        }
    }

    const int lr = lane >> 2, lc = (lane & 3) * 2;
    const bool wplanes = (jb.Ch != nullptr);
#pragma unroll
    for (int nt = 0; nt < 4; nt++) {
        int col = n0 + warp_n + nt * 8 + lc;
        float2 bv = *(const float2*)&jb.bias[col];
#pragma unroll
        for (int mt = 0; mt < 2; mt++) {
            int r0 = m0 + warp_m + mt * 16 + lr;
            float2 o0 = make_float2(acc[mt][nt][0] + bv.x, acc[mt][nt][1] + bv.y);
            float2 o1 = make_float2(acc[mt][nt][2] + bv.x, acc[mt][nt][3] + bv.y);
            *(float2*)(jb.C + (size_t)r0 * N + col) = o0;
            *(float2*)(jb.C + (size_t)(r0 + 8) * N + col) = o1;
            if (wplanes) {
                size_t i0 = (size_t)r0 * N + col;
                size_t i1 = (size_t)(r0 + 8) * N + col;
                *(uint32_t*)&jb.Ch[i0] = pack_hi(o0.x, o0.y);
                *(uint32_t*)&jb.Cl[i0] = pack_lo(o0.x, o0.y);
                *(uint32_t*)&jb.Ch[i1] = pack_hi(o1.x, o1.y);
                *(uint32_t*)&jb.Cl[i1] = pack_lo(o1.x, o1.y);
            }
        }
    }
}

// ---------------------------------------------------------------------------
// Fused attention with IN-KERNEL normalization epilogue.
// ---------------------------------------------------------------------------
#define QROWB 144
#define AQH   0
#define AQL   18432
#define AKH0  36864
#define AKH1  73728
#define AVH0  110592
#define AVH1  147456
#define SM2_TOT 184320

__global__ __launch_bounds__(256, 1)
void attn_fused_mma(float* __restrict__ attn)
{
    extern __shared__ __align__(128) char sm[];
    const uint32_t smb = smem_u32(sm);
    const int tid = threadIdx.x;
    const int wid = tid >> 5, lane = tid & 31;
    const int b = blockIdx.z, h = blockIdx.y;
    const int it = (int)gridDim.x - 1 - (int)blockIdx.x;
    const int r0 = it * 128;
    const int warp_m = wid * 16;
    const int lr = lane >> 2, lc2 = (lane & 3) * 2;
    const float CE = 0.125f * 1.4426950408889634f;

    const size_t qoff = ((size_t)b * Sc + r0) * Dc + h * DPc;
    const size_t koff = (size_t)b * Sc * Dc + h * DPc;
    const size_t bh_ = (size_t)(b * Hc + h);
    float* attnp = attn + bh_ * Sc * Sc;

    auto issue_plane = [&](uint32_t dst, const __nv_bfloat16* src) {
#pragma unroll
        for (int e = 0; e < 4; e++) {
            int idx = tid + e * 256;
            int r = idx >> 3, c = idx & 7;
            cpa16(dst + (uint32_t)(r * QROWB + c * 16), src + (size_t)r * Dc + c * 8);
        }
    };
    auto issue_K = [&](int jt) {
        uint32_t dst = smb + ((jt & 1) ? AKH1 : AKH0);
        const size_t off = koff + (size_t)jt * 128 * Dc;
        issue_plane(dst, g_kh + off);
        issue_plane(dst + 18432, g_kl + off);
    };
    auto issue_V = [&](int jt) {
        uint32_t dst = smb + ((jt & 1) ? AVH1 : AVH0);
        const size_t off = koff + (size_t)jt * 128 * Dc;
        issue_plane(dst, g_vh + off);
        issue_plane(dst + 18432, g_vl + off);
    };

    issue_plane(smb + AQH, g_qh + qoff);
    issue_plane(smb + AQL, g_ql + qoff);
    issue_K(0);
    CP_COMMIT();
    issue_V(0);
    CP_COMMIT();
    if (it >= 1) issue_K(1);
    CP_COMMIT();

    float ctx[8][4];
#pragma unroll
    for (int d = 0; d < 8; d++)
#pragma unroll
        for (int c = 0; c < 4; c++) ctx[d][c] = 0.0f;

    float lsum0 = 0.0f, lsum1 = 0.0f;

    const int arow = lane & 15;
    const int acol = (lane >> 4) * 8;
    const int bg = lane >> 3, bw = lane & 7;
    const int growg0 = r0 + warp_m + lr;
    const int growg1 = growg0 + 8;

    for (int jt = 0; jt <= it; jt++) {
        const int j0 = jt * 128;

        CP_WAITG(2);
        __syncthreads();

        if (jt + 1 <= it) issue_V(jt + 1);
        CP_COMMIT();

        const uint32_t kbase = (jt & 1) ? AKH1 : AKH0;

        float acc[16][4];
#pragma unroll
        for (int i = 0; i < 16; i++)
#pragma unroll
            for (int c = 0; c < 4; c++) acc[i][c] = 0.0f;

#pragma unroll
        for (int ks = 0; ks < 4; ks++) {
            const int k16 = ks * 16;
            uint32_t ah[4], al[4];
            {
                uint32_t off = (uint32_t)((warp_m + arow) * QROWB + (k16 + acol) * 2);
                ldsm4(ah, smb + AQH + off);
                ldsm4(al, smb + AQL + off);
            }
#pragma unroll
            for (int nb = 0; nb < 8; nb++) {
                uint32_t off = (uint32_t)((nb * 16 + (bg & 1) * 8 + bw) * QROWB
                                          + (k16 + (bg >> 1) * 8) * 2);
                uint32_t t[4], bh0[2], bh1[2], bl0[2], bl1[2];
                ldsm4(t, smb + kbase + off);
                bh0[0] = t[0]; bh0[1] = t[2];
                bh1[0] = t[1]; bh1[1] = t[3];
                ldsm4(t, smb + kbase + 18432 + off);
                bl0[0] = t[0]; bl0[1] = t[2];
                bl1[0] = t[1]; bl1[1] = t[3];
                mma16816(acc[nb * 2 + 0], ah, bh0);
                mma16816(acc[nb * 2 + 0], ah, bl0);
                mma16816(acc[nb * 2 + 0], al, bh0);
                mma16816(acc[nb * 2 + 1], ah, bh1);
                mma16816(acc[nb * 2 + 1], ah, bl1);
                mma16816(acc[nb * 2 + 1], al, bh1);
            }
        }

        const bool diag = (jt == it);
#pragma unroll
        for (int nt = 0; nt < 16; nt++) {
            const int col = j0 + nt * 8 + lc2;
            float p0 = fexp2(acc[nt][0] * CE);
            float p1 = fexp2(acc[nt][1] * CE);
            float p2 = fexp2(acc[nt][2] * CE);
            float p3 = fexp2(acc[nt][3] * CE);
            if (diag) {
                if (col + 0 > growg0) p0 = 0.0f;
                if (col + 1 > growg0) p1 = 0.0f;
                if (col + 0 > growg1) p2 = 0.0f;
                if (col + 1 > growg1) p3 = 0.0f;
            }
            *(float2*)&attnp[(size_t)growg0 * Sc + col] = make_float2(p0, p1);
            *(float2*)&attnp[(size_t)growg1 * Sc + col] = make_float2(p2, p3);
            acc[nt][0] = p0; acc[nt][1] = p1; acc[nt][2] = p2; acc[nt][3] = p3;
            lsum0 += p0 + p1;
            lsum1 += p2 + p3;
        }

        CP_WAITG(2);
        __syncthreads();

        if (jt + 2 <= it) issue_K(jt + 2);
        CP_COMMIT();

        const uint32_t vbase = (jt & 1) ? AVH1 : AVH0;

#pragma unroll
        for (int ks = 0; ks < 8; ks++) {
            uint32_t aph[4], apl[4];
            aph[0] = pack_hi(acc[ks * 2 + 0][0], acc[ks * 2 + 0][1]);
            aph[1] = pack_hi(acc[ks * 2 + 0][2], acc[ks * 2 + 0][3]);
            aph[2] = pack_hi(acc[ks * 2 + 1][0], acc[ks * 2 + 1][1]);
            aph[3] = pack_hi(acc[ks * 2 + 1][2], acc[ks * 2 + 1][3]);
            apl[0] = pack_lo(acc[ks * 2 + 0][0], acc[ks * 2 + 0][1]);
            apl[1] = pack_lo(acc[ks * 2 + 0][2], acc[ks * 2 + 0][3]);
            apl[2] = pack_lo(acc[ks * 2 + 1][0], acc[ks * 2 + 1][1]);
            apl[3] = pack_lo(acc[ks * 2 + 1][2], acc[ks * 2 + 1][3]);
#pragma unroll
            for (int d16 = 0; d16 < 4; d16++) {
                uint32_t voff = (uint32_t)((ks * 16 + (lane & 15)) * QROWB
                                           + (d16 * 16 + (lane >> 4) * 8) * 2);
                uint32_t t[4], vh0[2], vh1[2], vl0[2], vl1[2];
                ldsm4t(t, smb + vbase + voff);
                vh0[0] = t[0]; vh0[1] = t[1];
                vh1[0] = t[2]; vh1[1] = t[3];
                ldsm4t(t, smb + vbase + 18432 + voff);
                vl0[0] = t[0]; vl0[1] = t[1];
                vl1[0] = t[2]; vl1[1] = t[3];
                mma16816(ctx[d16 * 2 + 0], aph, vh0);
                mma16816(ctx[d16 * 2 + 0], aph, vl0);
                mma16816(ctx[d16 * 2 + 0], apl, vh0);
                mma16816(ctx[d16 * 2 + 1], aph, vh1);
                mma16816(ctx[d16 * 2 + 1], aph, vl1);
                mma16816(ctx[d16 * 2 + 1], apl, vh1);
            }
        }
    }

    // ---- per-warp row sums (rows exclusively owned by this warp)
#pragma unroll
    for (int off = 1; off <= 2; off <<= 1) {
        lsum0 += __shfl_xor_sync(0xffffffffu, lsum0, off);
        lsum1 += __shfl_xor_sync(0xffffffffu, lsum1, off);
    }
    const float inv0 = 1.0f / lsum0;
    const float inv1 = 1.0f / lsum1;

    // ---- normalized ctx -> bf16 hi/lo planes
#pragma unroll
    for (int d = 0; d < 8; d++) {
        int dcol = h * DPc + d * 8 + lc2;
        float x0 = ctx[d][0] * inv0, x1 = ctx[d][1] * inv0;
        float x2 = ctx[d][2] * inv1, x3 = ctx[d][3] * inv1;
        size_t i0 = ((size_t)b * Sc + growg0) * Dc + dcol;
        size_t i1 = ((size_t)b * Sc + growg1) * Dc + dcol;
        *(uint32_t*)&g_ch2[i0] = pack_hi(x0, x1);
        *(uint32_t*)&g_cl2[i0] = pack_lo(x0, x1);
        *(uint32_t*)&g_ch2[i1] = pack_hi(x2, x3);
        *(uint32_t*)&g_cl2[i1] = pack_lo(x2, x3);
    }

    // ---- in-place normalization of this warp's attn rows
    __syncthreads();   // make this block's attn stores visible to all its lanes
#pragma unroll 1
    for (int rr = 0; rr < 16; rr++) {
        const int row = r0 + warp_m + rr;
        const float invr = __shfl_sync(0xffffffffu,
                                       (rr < 8) ? inv0 : inv1, (rr & 7) * 4);
        float4* rowp = (float4*)&attnp[(size_t)row * Sc];
        for (int pass = 0; pass <= it; pass++) {
            int c4 = pass * 32 + lane;
            float4 v = rowp[c4];
            v.x *= invr; v.y *= invr; v.z *= invr; v.w *= invr;
            rowp[c4] = v;
        }
    }
}

// ---------------------------------------------------------------------------
__global__ __launch_bounds__(512, 2)
void fill_upper(float* __restrict__ attn)
{
    const int b = blockIdx.z, h = blockIdx.y, it = blockIdx.x;
    const int ncol4 = 512 - (it + 1) * 32;
    if (ncol4 <= 0) return;
    const int c0 = (it + 1) * 32;
    float* ap = attn + ((size_t)(b * Hc + h)) * Sc * Sc + (size_t)it * 128 * Sc;
    const float4 z = make_float4(0.f, 0.f, 0.f, 0.f);
    const int tid = threadIdx.x;
    const int total = 128 * ncol4;
    for (int i = tid; i < total; i += 512) {
        int r = i / ncol4, c = i - r * ncol4;
        ((float4*)&ap[(size_t)r * Sc])[c0 + c] = z;
    }
}

// ---------------------------------------------------------------------------
extern "C" void kernel_launch(void* const* d_in, const int* in_sizes, int n_in,
                              void* d_out, int out_size)
{
    (void)in_sizes; (void)n_in; (void)out_size;
    const float* Q   = (const float*)d_in[0];
    const float* Kin = (const float*)d_in[1];
    const float* Vin = (const float*)d_in[2];
    const float* Wq = (const float*)d_in[4];
    const float* bq = (const float*)d_in[5];
    const float* Wk = (const float*)d_in[6];
    const float* bk = (const float*)d_in[7];
    const float* Wv = (const float*)d_in[8];
    const float* bv = (const float*)d_in[9];
    const float* Wo = (const float*)d_in[10];
    const float* bo = (const float*)d_in[11];

    float* out  = (float*)d_out;
    float* attn = out + SZ_QKV;
    float* qo   = attn + SZ_ATTN;
    float* ko   = qo + SZ_QKV;
    float* vo   = ko + SZ_QKV;

    void *iah, *ial, *wh, *wl, *qh, *ql, *kh, *kl, *vh, *vl, *ch2, *cl2;
    cudaGetSymbolAddress(&iah, g_iah);  cudaGetSymbolAddress(&ial, g_ial);
    cudaGetSymbolAddress(&wh, g_wh);    cudaGetSymbolAddress(&wl, g_wl);
    cudaGetSymbolAddress(&qh, g_qh);    cudaGetSymbolAddress(&ql, g_ql);
    cudaGetSymbolAddress(&kh, g_kh);    cudaGetSymbolAddress(&kl, g_kl);
    cudaGetSymbolAddress(&vh, g_vh);    cudaGetSymbolAddress(&vl, g_vl);
    cudaGetSymbolAddress(&ch2, g_ch2);  cudaGetSymbolAddress(&cl2, g_cl2);
    __nv_bfloat16 *IAH = (__nv_bfloat16*)iah, *IAL = (__nv_bfloat16*)ial;
    __nv_bfloat16 *WH  = (__nv_bfloat16*)wh,  *WL  = (__nv_bfloat16*)wl;

    cudaFuncSetAttribute(gemm_bf16,
                         cudaFuncAttributeMaxDynamicSharedMemorySize, G2SM);
    cudaFuncSetAttribute(attn_fused_mma,
                         cudaFuncAttributeMaxDynamicSharedMemorySize, SM2_TOT);

    const int M = Bc * Sc;

    cudaStream_t s1;
    cudaStreamCreateWithFlags(&s1, cudaStreamNonBlocking);
    cudaEvent_t e0, e2;
    cudaEventCreateWithFlags(&e0, cudaEventDisableTiming);
    cudaEventCreateWithFlags(&e2, cudaEventDisableTiming);

    dim3 agrid(Sc / 128, Hc, Bc);

    // fork EARLY: fill_upper has no deps — overlaps converts + QKV gemm
    cudaEventRecord(e0, 0);
    cudaStreamWaitEvent(s1, e0, 0);
    fill_upper<<<agrid, 512, 0, s1>>>(attn);
    cudaEventRecord(e2, s1);

    // 1) converts
    ConvBatch cb;
    const float* srcs[7] = { Q, Kin, Vin, Wq, Wk, Wv, Wo };
    for (int z = 0; z < 7; z++) {
        cb.j[z].src = srcs[z];
        if (z < 3) {
            cb.j[z].h = IAH + (size_t)z * MD;
            cb.j[z].l = IAL + (size_t)z * MD;
            cb.j[z].n4 = (int)(MD / 4);
        } else {
            cb.j[z].h = WH + (size_t)(z - 3) * DD;
            cb.j[z].l = WL + (size_t)(z - 3) * DD;
            cb.j[z].n4 = (int)(DD / 4);
        }
    }
    dim3 cgrid((unsigned)((MD / 4 + 255) / 256), 1, 7);
    convert_all<<<cgrid, 256>>>(cb);

    // 2) QKV projections
    GemmBatch qb;
    const float* biases[3] = { bq, bk, bv };
    float* outs[3] = { qo, ko, vo };
    __nv_bfloat16* chp[3] = { (__nv_bfloat16*)qh, (__nv_bfloat16*)kh, (__nv_bfloat16*)vh };
    __nv_bfloat16* clp[3] = { (__nv_bfloat16*)ql, (__nv_bfloat16*)kl, (__nv_bfloat16*)vl };
    for (int z = 0; z < 3; z++) {
        qb.j[z].Ah = IAH + (size_t)z * MD; qb.j[z].Al = IAL + (size_t)z * MD;
        qb.j[z].Bh = WH + (size_t)z * DD;  qb.j[z].Bl = WL + (size_t)z * DD;
        qb.j[z].bias = biases[z]; qb.j[z].C = outs[z];
        qb.j[z].Ch = chp[z]; qb.j[z].Cl = clp[z];
    }
    dim3 qgrid(Dc / 128, M / 128, 3);
    gemm_bf16<<<qgrid, 512, G2SM>>>(qb, M, Dc, Dc);

    // 3) attention (normalizes its own attn strip in-kernel)
    attn_fused_mma<<<agrid, 256, SM2_TOT>>>(attn);

    // 4) O projection directly after attention
    GemmBatch ob;
    ob.j[0].Ah = (__nv_bfloat16*)ch2; ob.j[0].Al = (__nv_bfloat16*)cl2;
    ob.j[0].Bh = WH + 3 * DD;         ob.j[0].Bl = WL + 3 * DD;
    ob.j[0].bias = bo; ob.j[0].C = out;
    ob.j[0].Ch = nullptr; ob.j[0].Cl = nullptr;
    ob.j[1] = ob.j[0]; ob.j[2] = ob.j[0];
    dim3 ogrid(Dc / 128, M / 128, 1);
    gemm_bf16<<<ogrid, 512, G2SM>>>(ob, M, Dc, Dc);

    // join: fill_upper must be complete before harness reads attn
    cudaStreamWaitEvent(0, e2, 0);
}

// round 16
// speedup vs baseline: 1.1228x; 1.1228x over previous
#include <cuda_runtime.h>
#include <cuda_bf16.h>
#include <math.h>
#include <stdint.h>

#define Bc 2
#define Sc 2048
#define Dc 1024
#define Hc 16
#define DPc 64

static const size_t SZ_QKV  = (size_t)Bc * Sc * Dc;        // 4194304
static const size_t SZ_ATTN = (size_t)Bc * Hc * Sc * Sc;   // 134217728
#define MD  ((size_t)4194304)
#define DD  ((size_t)1048576)

__device__ __nv_bfloat16 g_iah[3 * MD], g_ial[3 * MD];
__device__ __nv_bfloat16 g_wh[4 * DD],  g_wl[4 * DD];
__device__ __nv_bfloat16 g_qh[MD], g_ql[MD];
__device__ __nv_bfloat16 g_kh[MD], g_kl[MD];
__device__ __nv_bfloat16 g_vh[MD], g_vl[MD];
__device__ __nv_bfloat16 g_ch2[MD], g_cl2[MD];
__device__ float g_lbuf[(size_t)Bc * Hc * Sc];

// ---------------------------------------------------------------------------
__device__ __forceinline__ uint32_t smem_u32(const void* p) {
    uint32_t a;
    asm("{ .reg .u64 t; cvta.to.shared.u64 t, %1; cvt.u32.u64 %0, t; }"
        : "=r"(a) : "l"(p));
    return a;
}
__device__ __forceinline__ void mma16816(float* d, const uint32_t* a, const uint32_t* b) {
    asm volatile(
        "mma.sync.aligned.m16n8k16.row.col.f32.bf16.bf16.f32 "
        "{%0,%1,%2,%3}, {%4,%5,%6,%7}, {%8,%9}, {%0,%1,%2,%3};"
        : "+f"(d[0]), "+f"(d[1]), "+f"(d[2]), "+f"(d[3])
        : "r"(a[0]), "r"(a[1]), "r"(a[2]), "r"(a[3]), "r"(b[0]), "r"(b[1]));
}
__device__ __forceinline__ void ldsm4(uint32_t* r, uint32_t addr) {
    asm volatile("ldmatrix.sync.aligned.m8n8.x4.shared.b16 {%0,%1,%2,%3}, [%4];"
                 : "=r"(r[0]), "=r"(r[1]), "=r"(r[2]), "=r"(r[3]) : "r"(addr));
}
__device__ __forceinline__ void ldsm4t(uint32_t* r, uint32_t addr) {
    asm volatile("ldmatrix.sync.aligned.m8n8.x4.trans.shared.b16 {%0,%1,%2,%3}, [%4];"
                 : "=r"(r[0]), "=r"(r[1]), "=r"(r[2]), "=r"(r[3]) : "r"(addr));
}
__device__ __forceinline__ float fexp2(float x) {
    float r;
    asm("ex2.approx.f32 %0, %1;" : "=f"(r) : "f"(x));
    return r;
}
__device__ __forceinline__ uint32_t pack_hi(float x, float y) {
    __nv_bfloat162 h = __float22bfloat162_rn(make_float2(x, y));
    return *(uint32_t*)&h;
}
__device__ __forceinline__ uint32_t pack_lo(float x, float y) {
    __nv_bfloat16 hx = __float2bfloat16(x), hy = __float2bfloat16(y);
    __nv_bfloat162 l = __float22bfloat162_rn(
        make_float2(x - __bfloat162float(hx), y - __bfloat162float(hy)));
    return *(uint32_t*)&l;
}
__device__ __forceinline__ void cpa16(uint32_t s, const void* g) {
    asm volatile("cp.async.cg.shared.global [%0], [%1], 16;" :: "r"(s), "l"(g));
}
#define CP_COMMIT()  asm volatile("cp.async.commit_group;" ::: "memory")
#define CP_WAITG(n)  asm volatile("cp.async.wait_group %0;" :: "n"(n) : "memory")

// ---------------------------------------------------------------------------
// converts
// ---------------------------------------------------------------------------
struct ConvJob { const float* src; __nv_bfloat16 *h, *l; int n4; };
struct ConvBatch { ConvJob j[7]; };

__global__ __launch_bounds__(256, 4)
void convert_all(ConvBatch cb)
{
    ConvJob jb = cb.j[blockIdx.z];
    int i = blockIdx.x * 256 + threadIdx.x;
    if (i >= jb.n4) return;
    float4 v = ((const float4*)jb.src)[i];
    uint2 H, L;
    H.x = pack_hi(v.x, v.y); H.y = pack_hi(v.z, v.w);
    L.x = pack_lo(v.x, v.y); L.y = pack_lo(v.z, v.w);
    ((uint2*)jb.h)[i] = H;
    ((uint2*)jb.l)[i] = L;
}

// ---------------------------------------------------------------------------
// GEMM v2.1 (unchanged from R14)
// ---------------------------------------------------------------------------
#define G2ROWB 144
#define G2PLANE (128 * G2ROWB)
#define G2STAGE (4 * G2PLANE)
#define G2SM   (3 * G2STAGE)

struct GemmJob {
    const __nv_bfloat16 *Ah, *Al, *Bh, *Bl;
    const float* bias;
    float* C;
    __nv_bfloat16 *Ch, *Cl;
};
struct GemmBatch { GemmJob j[3]; };

__global__ __launch_bounds__(512, 1)
void gemm_bf16(GemmBatch gb, int M, int N, int K)
{
    extern __shared__ __align__(128) char sm[];
    const uint32_t smb = smem_u32(sm);
    const GemmJob jb = gb.j[blockIdx.z];
    const int tid = threadIdx.x;
    const int wid = tid >> 5, lane = tid & 31;
    const int m0 = blockIdx.y * 128, n0 = blockIdx.x * 128;
    const int warp_m = (wid & 3) * 32;
    const int warp_n = (wid >> 2) * 32;
    const int nch = K / 64;

    const __nv_bfloat16* bases[4] = { jb.Ah, jb.Al, jb.Bh, jb.Bl };

    auto issue = [&](int ch) {
        const uint32_t sb = smb + (uint32_t)((ch % 3) * G2STAGE);
        const size_t gk = (size_t)ch * 64;
#pragma unroll
        for (int p = 0; p < 4; p++) {
            const int rbase = (p < 2) ? m0 : n0;
#pragma unroll
            for (int e = 0; e < 2; e++) {
                int idx = tid + e * 512;
                int r = idx >> 3, c = idx & 7;
                cpa16(sb + (uint32_t)(p * G2PLANE + r * G2ROWB + c * 16),
                      bases[p] + (size_t)(rbase + r) * K + gk + c * 8);
            }
        }
    };

    float acc[2][4][4];
#pragma unroll
    for (int i = 0; i < 2; i++)
#pragma unroll
        for (int j = 0; j < 4; j++)
#pragma unroll
            for (int c = 0; c < 4; c++) acc[i][j][c] = 0.0f;

    issue(0); CP_COMMIT();
    issue(1); CP_COMMIT();

    const int arow = lane & 15;
    const int acol = (lane >> 4) * 8;
    const int bg = lane >> 3, bw = lane & 7;

    for (int ch = 0; ch < nch; ch++) {
        CP_WAITG(1);
        __syncthreads();
        if (ch + 2 < nch) issue(ch + 2);
        CP_COMMIT();

        const uint32_t sb = smb + (uint32_t)((ch % 3) * G2STAGE);
#pragma unroll
        for (int ks = 0; ks < 4; ks++) {
            const int k16 = ks * 16;
            uint32_t ah[2][4], al[2][4];
#pragma unroll
            for (int mt = 0; mt < 2; mt++) {
                uint32_t off = (uint32_t)((warp_m + mt * 16 + arow) * G2ROWB
                                          + (k16 + acol) * 2);
                ldsm4(ah[mt], sb + 0 * G2PLANE + off);
                ldsm4(al[mt], sb + 1 * G2PLANE + off);
            }
            uint32_t bh[4][2], bl[4][2];
#pragma unroll
            for (int nb = 0; nb < 2; nb++) {
                uint32_t off = (uint32_t)((warp_n + nb * 16 + (bg & 1) * 8 + bw) * G2ROWB
                                          + (k16 + (bg >> 1) * 8) * 2);
                uint32_t t[4];
                ldsm4(t, sb + 2 * G2PLANE + off);
                bh[nb * 2 + 0][0] = t[0]; bh[nb * 2 + 0][1] = t[2];
                bh[nb * 2 + 1][0] = t[1]; bh[nb * 2 + 1][1] = t[3];
                ldsm4(t, sb + 3 * G2PLANE + off);
                bl[nb * 2 + 0][0] = t[0]; bl[nb * 2 + 0][1] = t[2];
                bl[nb * 2 + 1][0] = t[1]; bl[nb * 2 + 1][1] = t[3];
            }
#pragma unroll
            for (int mt = 0; mt < 2; mt++)
#pragma unroll
                for (int nt = 0; nt < 4; nt++) {
                    mma16816(acc[mt][nt], ah[mt], bh[nt]);
                    mma16816(acc[mt][nt], ah[mt], bl[nt]);
                    mma16816(acc[mt][nt], al[mt], bh[nt]);
                }
        }
    }

    const int lr = lane >> 2, lc = (lane & 3) * 2;
    const bool wplanes = (jb.Ch != nullptr);
#pragma unroll
    for (int nt = 0; nt < 4; nt++) {
        int col = n0 + warp_n + nt * 8 + lc;
        float2 bv = *(const float2*)&jb.bias[col];
#pragma unroll
        for (int mt = 0; mt < 2; mt++) {
            int r0 = m0 + warp_m + mt * 16 + lr;
            float2 o0 = make_float2(acc[mt][nt][0] + bv.x, acc[mt][nt][1] + bv.y);
            float2 o1 = make_float2(acc[mt][nt][2] + bv.x, acc[mt][nt][3] + bv.y);
            *(float2*)(jb.C + (size_t)r0 * N + col) = o0;
            *(float2*)(jb.C + (size_t)(r0 + 8) * N + col) = o1;
            if (wplanes) {
                size_t i0 = (size_t)r0 * N + col;
                size_t i1 = (size_t)(r0 + 8) * N + col;
                *(uint32_t*)&jb.Ch[i0] = pack_hi(o0.x, o0.y);
                *(uint32_t*)&jb.Cl[i0] = pack_lo(o0.x, o0.y);
                *(uint32_t*)&jb.Ch[i1] = pack_hi(o1.x, o1.y);
                *(uint32_t*)&jb.Cl[i1] = pack_lo(o1.x, o1.y);
            }
        }
    }
}

// ---------------------------------------------------------------------------
// Fused attention (R14 version), parameterized by tile-range offset it0.
// ---------------------------------------------------------------------------
#define QROWB 144
#define AQH   0
#define AQL   18432
#define AKH0  36864
#define AKH1  73728
#define AVH0  110592
#define AVH1  147456
#define SM2_TOT 184320

__global__ __launch_bounds__(256, 1)
void attn_fused_mma(float* __restrict__ attn, int it0)
{
    extern __shared__ __align__(128) char sm[];
    const uint32_t smb = smem_u32(sm);
    const int tid = threadIdx.x;
    const int wid = tid >> 5, lane = tid & 31;
    const int b = blockIdx.z, h = blockIdx.y;
    const int it = it0 + (int)gridDim.x - 1 - (int)blockIdx.x;  // big first
    const int r0 = it * 128;
    const int warp_m = wid * 16;
    const int lr = lane >> 2, lc2 = (lane & 3) * 2;
    const float CE = 0.125f * 1.4426950408889634f;

    const size_t qoff = ((size_t)b * Sc + r0) * Dc + h * DPc;
    const size_t koff = (size_t)b * Sc * Dc + h * DPc;
    const size_t bh_ = (size_t)(b * Hc + h);
    float* attnp = attn + bh_ * Sc * Sc;

    auto issue_plane = [&](uint32_t dst, const __nv_bfloat16* src) {
#pragma unroll
        for (int e = 0; e < 4; e++) {
            int idx = tid + e * 256;
            int r = idx >> 3, c = idx & 7;
            cpa16(dst + (uint32_t)(r * QROWB + c * 16), src + (size_t)r * Dc + c * 8);
        }
    };
    auto issue_K = [&](int jt) {
        uint32_t dst = smb + ((jt & 1) ? AKH1 : AKH0);
        const size_t off = koff + (size_t)jt * 128 * Dc;
        issue_plane(dst, g_kh + off);
        issue_plane(dst + 18432, g_kl + off);
    };
    auto issue_V = [&](int jt) {
        uint32_t dst = smb + ((jt & 1) ? AVH1 : AVH0);
        const size_t off = koff + (size_t)jt * 128 * Dc;
        issue_plane(dst, g_vh + off);
        issue_plane(dst + 18432, g_vl + off);
    };

    issue_plane(smb + AQH, g_qh + qoff);
    issue_plane(smb + AQL, g_ql + qoff);
    issue_K(0);
    CP_COMMIT();
    issue_V(0);
    CP_COMMIT();
    if (it >= 1) issue_K(1);
    CP_COMMIT();

    float ctx[8][4];
#pragma unroll
    for (int d = 0; d < 8; d++)
#pragma unroll
        for (int c = 0; c < 4; c++) ctx[d][c] = 0.0f;

    float lsum0 = 0.0f, lsum1 = 0.0f;

    const int arow = lane & 15;
    const int acol = (lane >> 4) * 8;
    const int bg = lane >> 3, bw = lane & 7;
    const int growg0 = r0 + warp_m + lr;
    const int growg1 = growg0 + 8;

    for (int jt = 0; jt <= it; jt++) {
        const int j0 = jt * 128;

        CP_WAITG(2);
        __syncthreads();

        if (jt + 1 <= it) issue_V(jt + 1);
        CP_COMMIT();

        const uint32_t kbase = (jt & 1) ? AKH1 : AKH0;

        float acc[16][4];
#pragma unroll
        for (int i = 0; i < 16; i++)
#pragma unroll
            for (int c = 0; c < 4; c++) acc[i][c] = 0.0f;

#pragma unroll
        for (int ks = 0; ks < 4; ks++) {
            const int k16 = ks * 16;
            uint32_t ah[4], al[4];
            {
                uint32_t off = (uint32_t)((warp_m + arow) * QROWB + (k16 + acol) * 2);
                ldsm4(ah, smb + AQH + off);
                ldsm4(al, smb + AQL + off);
            }
#pragma unroll
            for (int nb = 0; nb < 8; nb++) {
                uint32_t off = (uint32_t)((nb * 16 + (bg & 1) * 8 + bw) * QROWB
                                          + (k16 + (bg >> 1) * 8) * 2);
                uint32_t t[4], bh0[2], bh1[2], bl0[2], bl1[2];
                ldsm4(t, smb + kbase + off);
                bh0[0] = t[0]; bh0[1] = t[2];
                bh1[0] = t[1]; bh1[1] = t[3];
                ldsm4(t, smb + kbase + 18432 + off);
                bl0[0] = t[0]; bl0[1] = t[2];
                bl1[0] = t[1]; bl1[1] = t[3];
                mma16816(acc[nb * 2 + 0], ah, bh0);
                mma16816(acc[nb * 2 + 0], ah, bl0);
                mma16816(acc[nb * 2 + 0], al, bh0);
                mma16816(acc[nb * 2 + 1], ah, bh1);
                mma16816(acc[nb * 2 + 1], ah, bl1);
                mma16816(acc[nb * 2 + 1], al, bh1);
            }
        }

        const bool diag = (jt == it);
#pragma unroll
        for (int nt = 0; nt < 16; nt++) {
            const int col = j0 + nt * 8 + lc2;
            float p0 = fexp2(acc[nt][0] * CE);
            float p1 = fexp2(acc[nt][1] * CE);
            float p2 = fexp2(acc[nt][2] * CE);
            float p3 = fexp2(acc[nt][3] * CE);
            if (diag) {
                if (col + 0 > growg0) p0 = 0.0f;
                if (col + 1 > growg0) p1 = 0.0f;
                if (col + 0 > growg1) p2 = 0.0f;
                if (col + 1 > growg1) p3 = 0.0f;
            }
            *(float2*)&attnp[(size_t)growg0 * Sc + col] = make_float2(p0, p1);
            *(float2*)&attnp[(size_t)growg1 * Sc + col] = make_float2(p2, p3);
            acc[nt][0] = p0; acc[nt][1] = p1; acc[nt][2] = p2; acc[nt][3] = p3;
            lsum0 += p0 + p1;
            lsum1 += p2 + p3;
        }

        CP_WAITG(2);
        __syncthreads();

        if (jt + 2 <= it) issue_K(jt + 2);
        CP_COMMIT();

        const uint32_t vbase = (jt & 1) ? AVH1 : AVH0;

#pragma unroll
        for (int ks = 0; ks < 8; ks++) {
            uint32_t aph[4], apl[4];
            aph[0] = pack_hi(acc[ks * 2 + 0][0], acc[ks * 2 + 0][1]);
            aph[1] = pack_hi(acc[ks * 2 + 0][2], acc[ks * 2 + 0][3]);
            aph[2] = pack_hi(acc[ks * 2 + 1][0], acc[ks * 2 + 1][1]);
            aph[3] = pack_hi(acc[ks * 2 + 1][2], acc[ks * 2 + 1][3]);
            apl[0] = pack_lo(acc[ks * 2 + 0][0], acc[ks * 2 + 0][1]);
            apl[1] = pack_lo(acc[ks * 2 + 0][2], acc[ks * 2 + 0][3]);
            apl[2] = pack_lo(acc[ks * 2 + 1][0], acc[ks * 2 + 1][1]);
            apl[3] = pack_lo(acc[ks * 2 + 1][2], acc[ks * 2 + 1][3]);
#pragma unroll
            for (int d16 = 0; d16 < 4; d16++) {
                uint32_t voff = (uint32_t)((ks * 16 + (lane & 15)) * QROWB
                                           + (d16 * 16 + (lane >> 4) * 8) * 2);
                uint32_t t[4], vh0[2], vh1[2], vl0[2], vl1[2];
                ldsm4t(t, smb + vbase + voff);
                vh0[0] = t[0]; vh0[1] = t[1];
                vh1[0] = t[2]; vh1[1] = t[3];
                ldsm4t(t, smb + vbase + 18432 + voff);
                vl0[0] = t[0]; vl0[1] = t[1];
                vl1[0] = t[2]; vl1[1] = t[3];
                mma16816(ctx[d16 * 2 + 0], aph, vh0);
                mma16816(ctx[d16 * 2 + 0], aph, vl0);
                mma16816(ctx[d16 * 2 + 0], apl, vh0);
                mma16816(ctx[d16 * 2 + 1], aph, vh1);
                mma16816(ctx[d16 * 2 + 1], aph, vl1);
                mma16816(ctx[d16 * 2 + 1], apl, vh1);
            }
        }
    }

#pragma unroll
    for (int off = 1; off <= 2; off <<= 1) {
        lsum0 += __shfl_xor_sync(0xffffffffu, lsum0, off);
        lsum1 += __shfl_xor_sync(0xffffffffu, lsum1, off);
    }
    if ((lane & 3) == 0) {
        g_lbuf[bh_ * Sc + growg0] = lsum0;
        g_lbuf[bh_ * Sc + growg1] = lsum1;
    }
    const float inv0 = 1.0f / lsum0;
    const float inv1 = 1.0f / lsum1;

#pragma unroll
    for (int d = 0; d < 8; d++) {
        int dcol = h * DPc + d * 8 + lc2;
        float x0 = ctx[d][0] * inv0, x1 = ctx[d][1] * inv0;
        float x2 = ctx[d][2] * inv1, x3 = ctx[d][3] * inv1;
        size_t i0 = ((size_t)b * Sc + growg0) * Dc + dcol;
        size_t i1 = ((size_t)b * Sc + growg1) * Dc + dcol;
        *(uint32_t*)&g_ch2[i0] = pack_hi(x0, x1);
        *(uint32_t*)&g_cl2[i0] = pack_lo(x0, x1);
        *(uint32_t*)&g_ch2[i1] = pack_hi(x2, x3);
        *(uint32_t*)&g_cl2[i1] = pack_lo(x2, x3);
    }
}

// ---------------------------------------------------------------------------
__global__ __launch_bounds__(512, 2)
void fill_upper(float* __restrict__ attn)
{
    const int b = blockIdx.z, h = blockIdx.y, it = blockIdx.x;
    const int ncol4 = 512 - (it + 1) * 32;
    if (ncol4 <= 0) return;
    const int c0 = (it + 1) * 32;
    float* ap = attn + ((size_t)(b * Hc + h)) * Sc * Sc + (size_t)it * 128 * Sc;
    const float4 z = make_float4(0.f, 0.f, 0.f, 0.f);
    const int tid = threadIdx.x;
    const int total = 128 * ncol4;
    for (int i = tid; i < total; i += 512) {
        int r = i / ncol4, c = i - r * ncol4;
        ((float4*)&ap[(size_t)r * Sc])[c0 + c] = z;
    }
}

__global__ __launch_bounds__(512, 2)
void norm_lower(float* __restrict__ attn, int it0)
{
    const int b = blockIdx.z, h = blockIdx.y, it = it0 + blockIdx.x;
    const int r0 = it * 128;
    const int tid = threadIdx.x;
    const size_t bh_ = (size_t)(b * Hc + h);
    float* ap = attn + bh_ * Sc * Sc;

    __shared__ float inv[128];
    if (tid < 128) inv[tid] = 1.0f / g_lbuf[bh_ * Sc + r0 + tid];
    __syncthreads();

    const int ncol4 = (it + 1) * 32;
    for (int r = tid >> 7; r < 128; r += 4) {
        const float s = inv[r];
        float4* rowp = (float4*)&ap[(size_t)(r0 + r) * Sc];
#pragma unroll 4
        for (int c4 = (tid & 127); c4 < ncol4; c4 += 128) {
            float4 v = rowp[c4];
            v.x *= s; v.y *= s; v.z *= s; v.w *= s;
            rowp[c4] = v;
        }
    }
}

// ---------------------------------------------------------------------------
extern "C" void kernel_launch(void* const* d_in, const int* in_sizes, int n_in,
                              void* d_out, int out_size)
{
    (void)in_sizes; (void)n_in; (void)out_size;
    const float* Q   = (const float*)d_in[0];
    const float* Kin = (const float*)d_in[1];
    const float* Vin = (const float*)d_in[2];
    const float* Wq = (const float*)d_in[4];
    const float* bq = (const float*)d_in[5];
    const float* Wk = (const float*)d_in[6];
    const float* bk = (const float*)d_in[7];
    const float* Wv = (const float*)d_in[8];
    const float* bv = (const float*)d_in[9];
    const float* Wo = (const float*)d_in[10];
    const float* bo = (const float*)d_in[11];

    float* out  = (float*)d_out;
    float* attn = out + SZ_QKV;
    float* qo   = attn + SZ_ATTN;
    float* ko   = qo + SZ_QKV;
    float* vo   = ko + SZ_QKV;

    void *iah, *ial, *wh, *wl, *qh, *ql, *kh, *kl, *vh, *vl, *ch2, *cl2;
    cudaGetSymbolAddress(&iah, g_iah);  cudaGetSymbolAddress(&ial, g_ial);
    cudaGetSymbolAddress(&wh, g_wh);    cudaGetSymbolAddress(&wl, g_wl);
    cudaGetSymbolAddress(&qh, g_qh);    cudaGetSymbolAddress(&ql, g_ql);
    cudaGetSymbolAddress(&kh, g_kh);    cudaGetSymbolAddress(&kl, g_kl);
    cudaGetSymbolAddress(&vh, g_vh);    cudaGetSymbolAddress(&vl, g_vl);
    cudaGetSymbolAddress(&ch2, g_ch2);  cudaGetSymbolAddress(&cl2, g_cl2);
    __nv_bfloat16 *IAH = (__nv_bfloat16*)iah, *IAL = (__nv_bfloat16*)ial;
    __nv_bfloat16 *WH  = (__nv_bfloat16*)wh,  *WL  = (__nv_bfloat16*)wl;

    cudaFuncSetAttribute(gemm_bf16,
                         cudaFuncAttributeMaxDynamicSharedMemorySize, G2SM);
    cudaFuncSetAttribute(attn_fused_mma,
                         cudaFuncAttributeMaxDynamicSharedMemorySize, SM2_TOT);

    const int M = Bc * Sc;
    const int SPLIT = 6;          // tiles [SPLIT,16) first, then [0,SPLIT)

    cudaStream_t s1;
    cudaStreamCreateWithFlags(&s1, cudaStreamNonBlocking);
    cudaEvent_t e0, e1a, e1b, e2;
    cudaEventCreateWithFlags(&e0, cudaEventDisableTiming);
    cudaEventCreateWithFlags(&e1a, cudaEventDisableTiming);
    cudaEventCreateWithFlags(&e1b, cudaEventDisableTiming);
    cudaEventCreateWithFlags(&e2, cudaEventDisableTiming);

    // fork EARLY: fill_upper has no deps — overlaps converts + QKV gemm
    cudaEventRecord(e0, 0);
    cudaStreamWaitEvent(s1, e0, 0);
    dim3 fgrid(Sc / 128, Hc, Bc);
    fill_upper<<<fgrid, 512, 0, s1>>>(attn);

    // 1) converts
    ConvBatch cb;
    const float* srcs[7] = { Q, Kin, Vin, Wq, Wk, Wv, Wo };
    for (int z = 0; z < 7; z++) {
        cb.j[z].src = srcs[z];
        if (z < 3) {
            cb.j[z].h = IAH + (size_t)z * MD;
            cb.j[z].l = IAL + (size_t)z * MD;
            cb.j[z].n4 = (int)(MD / 4);
        } else {
            cb.j[z].h = WH + (size_t)(z - 3) * DD;
            cb.j[z].l = WL + (size_t)(z - 3) * DD;
            cb.j[z].n4 = (int)(DD / 4);
        }
    }
    dim3 cgrid((unsigned)((MD / 4 + 255) / 256), 1, 7);
    convert_all<<<cgrid, 256>>>(cb);

    // 2) QKV projections
    GemmBatch qb;
    const float* biases[3] = { bq, bk, bv };
    float* outs[3] = { qo, ko, vo };
    __nv_bfloat16* chp[3] = { (__nv_bfloat16*)qh, (__nv_bfloat16*)kh, (__nv_bfloat16*)vh };
    __nv_bfloat16* clp[3] = { (__nv_bfloat16*)ql, (__nv_bfloat16*)kl, (__nv_bfloat16*)vl };
    for (int z = 0; z < 3; z++) {
        qb.j[z].Ah = IAH + (size_t)z * MD; qb.j[z].Al = IAL + (size_t)z * MD;
        qb.j[z].Bh = WH + (size_t)z * DD;  qb.j[z].Bl = WL + (size_t)z * DD;
        qb.j[z].bias = biases[z]; qb.j[z].C = outs[z];
        qb.j[z].Ch = chp[z]; qb.j[z].Cl = clp[z];
    }
    dim3 qgrid(Dc / 128, M / 128, 3);
    gemm_bf16<<<qgrid, 512, G2SM>>>(qb, M, Dc, Dc);

    // 3a) attention: big tiles first
    dim3 agrid1(Sc / 128 - SPLIT, Hc, Bc);
    attn_fused_mma<<<agrid1, 256, SM2_TOT>>>(attn, SPLIT);
    cudaEventRecord(e1a, 0);

    // norm of big tiles overlaps small-tile attention + O-GEMM
    cudaStreamWaitEvent(s1, e1a, 0);
    norm_lower<<<agrid1, 512, 0, s1>>>(attn, SPLIT);

    // 3b) attention: small tiles
    dim3 agrid2(SPLIT, Hc, Bc);
    attn_fused_mma<<<agrid2, 256, SM2_TOT>>>(attn, 0);
    cudaEventRecord(e1b, 0);

    // norm of small tiles overlaps O-GEMM
    cudaStreamWaitEvent(s1, e1b, 0);
    norm_lower<<<agrid2, 512, 0, s1>>>(attn, 0);
    cudaEventRecord(e2, s1);

    // 4) O projection (needs all ctx; stream-ordered after 3b)
    GemmBatch ob;
    ob.j[0].Ah = (__nv_bfloat16*)ch2; ob.j[0].Al = (__nv_bfloat16*)cl2;
    ob.j[0].Bh = WH + 3 * DD;         ob.j[0].Bl = WL + 3 * DD;
    ob.j[0].bias = bo; ob.j[0].C = out;
    ob.j[0].Ch = nullptr; ob.j[0].Cl = nullptr;
    ob.j[1] = ob.j[0]; ob.j[2] = ob.j[0];
    dim3 ogrid(Dc / 128, M / 128, 1);
    gemm_bf16<<<ogrid, 512, G2SM>>>(ob, M, Dc, Dc);

    // join
    cudaStreamWaitEvent(0, e2, 0);
}